// round 13
// baseline (speedup 1.0000x reference)
#include <cuda_runtime.h>
#include <cuda_bf16.h>
#include <math.h>

// Problem constants
#define NN     4096
#define EE     32768
#define ALPHA  0.125f
#define INV_SQRT3 0.57735026918962576f

// Scratch (device globals: no runtime allocation allowed)
__device__ float g_h[(size_t)EE * 128];     // 16 MB: relu(edge_attr @ W1 + b1), tf32-rounded
__device__ float g_w2t[64 * 8192];          // 2 MB: W2 repacked per-chunk [x][pk], tf32-rounded
__device__ float g_acc[(size_t)NN * 96];    // residual + scattered messages
__device__ float g_scale[64];
__device__ float g_shift[48];
__device__ int   g_src[EE];
__device__ int   g_dst[EE];
__device__ int   g_i64;

// ---------------------------------------------------------------------------
// helpers
// ---------------------------------------------------------------------------
__device__ __forceinline__ float to_tf32(float x) {
    float r; asm("cvt.rna.tf32.f32 %0, %1;" : "=f"(r) : "f"(x)); return r;
}
__device__ __forceinline__ void mma_tf32(float* d, const unsigned* a, uint2 b) {
    asm volatile("mma.sync.aligned.m16n8k8.row.col.f32.tf32.tf32.f32 "
                 "{%0,%1,%2,%3}, {%4,%5,%6,%7}, {%8,%9}, {%0,%1,%2,%3};\n"
                 : "+f"(d[0]), "+f"(d[1]), "+f"(d[2]), "+f"(d[3])
                 : "r"(a[0]), "r"(a[1]), "r"(a[2]), "r"(a[3]),
                   "r"(b.x), "r"(b.y));
}
__device__ __forceinline__ void cp_async16(unsigned smem, const void* gmem) {
    asm volatile("cp.async.cg.shared.global [%0], [%1], 16;\n" :: "r"(smem), "l"(gmem));
}

// ---------------------------------------------------------------------------
// K-1a: detect edge_index dtype (int32 vs int64 little-endian)
// ---------------------------------------------------------------------------
__global__ void k_detect(const int* __restrict__ buf) {
    __shared__ int nz;
    if (threadIdx.x == 0) nz = 0;
    __syncthreads();
    int c = 0;
    for (int i = threadIdx.x; i < 2048; i += 256)
        if (buf[2 * i + 1] != 0) c++;
    if (c) atomicAdd(&nz, c);
    __syncthreads();
    if (threadIdx.x == 0) g_i64 = (nz == 0) ? 1 : 0;
}

// K-1b: unpack edge indices into int32 arrays (clamped defensively)
__global__ void k_unpack(const int* __restrict__ buf) {
    int e = blockIdx.x * 256 + threadIdx.x;
    int i64 = g_i64;
    int s = i64 ? buf[2 * e]          : buf[e];
    int d = i64 ? buf[2 * EE + 2 * e] : buf[EE + e];
    g_src[e] = min(max(s, 0), NN - 1);
    g_dst[e] = min(max(d, 0), NN - 1);
}

// ---------------------------------------------------------------------------
// K0: init accumulator with node_attr (residual)
// ---------------------------------------------------------------------------
__global__ void k0_init(const float* __restrict__ node_attr) {
    int idx = blockIdx.x * 256 + threadIdx.x;
    g_acc[idx] = node_attr[idx];
}

// ---------------------------------------------------------------------------
// K_w2t: one-time repack of W2 (128 x 4096) into per-chunk [x=64][pk=128]
// blocks, tf32-rounded.  pk(k) = (k>>3)*8 + (k&3)*2 + ((k>>2)&1) makes the
// two k-halves of each tf32 B-fragment adjacent -> LDS.64 in K2 mainloop.
// ---------------------------------------------------------------------------
__global__ __launch_bounds__(256) void k_w2t(const float* __restrict__ W2) {
    __shared__ float sm[128 * 69];   // [k][x] stride 69
    const int cc = blockIdx.x, tid = threadIdx.x;
    #pragma unroll
    for (int it = 0; it < 8; ++it) {
        int p = it * 1024 + tid * 4;
        int r = p >> 6, x = p & 63;
        float4 v = *(const float4*)(W2 + (size_t)r * 4096 + cc * 64 + x);
        sm[r * 69 + x + 0] = v.x;
        sm[r * 69 + x + 1] = v.y;
        sm[r * 69 + x + 2] = v.z;
        sm[r * 69 + x + 3] = v.w;
    }
    __syncthreads();
    #pragma unroll
    for (int it = 0; it < 8; ++it) {
        int q = it * 1024 + tid * 4;
        int x = q >> 7, pk0 = q & 127;
        float4 o;
        float* op = (float*)&o;
        #pragma unroll
        for (int l = 0; l < 4; ++l) {
            int pk = pk0 + l;
            int k = (pk >> 3) * 8 + (pk & 1) * 4 + ((pk & 7) >> 1);
            op[l] = to_tf32(sm[k * 69 + x]);
        }
        *(float4*)(g_w2t + (size_t)cc * 8192 + q) = o;
    }
}

// ---------------------------------------------------------------------------
// K1: h = relu(edge_attr @ W1 + b1)   (E x 128 x 128) — fp32 FFMA,
//     output tf32-rounded.  smem 100.4 KB x 2 CTAs = 200.7 KB <= 228 KB,
//     so 2 CTAs/SM (16 warps) for latency hiding.
// ---------------------------------------------------------------------------
#define K1_SMEM ((128*68 + 128*128) * 4)
__global__ __launch_bounds__(256, 2) void k1_gemm(const float* __restrict__ ea,
                                                  const float* __restrict__ W1,
                                                  const float* __restrict__ b1) {
    extern __shared__ float smem[];
    float* sh_aT = smem;              // [c][e], stride 68
    float* sh_w1 = smem + 128 * 68;   // [c][o], stride 128

    const int tid = threadIdx.x;
    const int e0  = blockIdx.x * 64;
    const int ty  = tid >> 4, tx = tid & 15;

    #pragma unroll
    for (int it = 0; it < 8; ++it) {
        int p = it * 1024 + tid * 4;
        int e = p >> 7, c = p & 127;
        float4 v = *(const float4*)(ea + (size_t)(e0 + e) * 128 + c);
        sh_aT[(c + 0) * 68 + e] = v.x;
        sh_aT[(c + 1) * 68 + e] = v.y;
        sh_aT[(c + 2) * 68 + e] = v.z;
        sh_aT[(c + 3) * 68 + e] = v.w;
    }
    #pragma unroll
    for (int it = 0; it < 16; ++it) {
        int p = it * 1024 + tid * 4;
        *(float4*)&sh_w1[p] = *(const float4*)(W1 + p);
    }
    __syncthreads();

    float acc[4][8];
    #pragma unroll
    for (int i = 0; i < 4; ++i)
        #pragma unroll
        for (int j = 0; j < 8; ++j) acc[i][j] = 0.f;

    #pragma unroll 4
    for (int c = 0; c < 128; ++c) {
        float4 a  = *(const float4*)&sh_aT[c * 68 + ty * 4];
        float4 w0 = *(const float4*)&sh_w1[c * 128 + tx * 8];
        float4 w1v= *(const float4*)&sh_w1[c * 128 + tx * 8 + 4];
        const float av[4] = {a.x, a.y, a.z, a.w};
        const float bv[8] = {w0.x, w0.y, w0.z, w0.w, w1v.x, w1v.y, w1v.z, w1v.w};
        #pragma unroll
        for (int i = 0; i < 4; ++i)
            #pragma unroll
            for (int j = 0; j < 8; ++j) acc[i][j] += av[i] * bv[j];
    }

    float4 bb0 = *(const float4*)(b1 + tx * 8);
    float4 bb1 = *(const float4*)(b1 + tx * 8 + 4);
    const float bias[8] = {bb0.x, bb0.y, bb0.z, bb0.w, bb1.x, bb1.y, bb1.z, bb1.w};
    #pragma unroll
    for (int i = 0; i < 4; ++i) {
        size_t row = (size_t)(e0 + ty * 4 + i) * 128 + tx * 8;
        float4 o0, o1;
        o0.x = to_tf32(fmaxf(acc[i][0] + bias[0], 0.f));
        o0.y = to_tf32(fmaxf(acc[i][1] + bias[1], 0.f));
        o0.z = to_tf32(fmaxf(acc[i][2] + bias[2], 0.f));
        o0.w = to_tf32(fmaxf(acc[i][3] + bias[3], 0.f));
        o1.x = to_tf32(fmaxf(acc[i][4] + bias[4], 0.f));
        o1.y = to_tf32(fmaxf(acc[i][5] + bias[5], 0.f));
        o1.z = to_tf32(fmaxf(acc[i][6] + bias[6], 0.f));
        o1.w = to_tf32(fmaxf(acc[i][7] + bias[7], 0.f));
        *(float4*)(g_h + row)     = o0;
        *(float4*)(g_h + row + 4) = o1;
    }
}

// ---------------------------------------------------------------------------
// K2: fused  w = dlrelu(h @ W2 + b2)  (tf32 mma)  +  per-edge contraction.
// A-fragments hoisted to registers; W2 streamed via cp.async into a SINGLE
// smem buffer; 2 CTAs/SM.  Gather ownership is grouped by warp pairs
// {wm, wm+4}: the pair that WRITES w-rows [16wm,16wm+16) is the pair that
// GATHERS them, so the per-chunk MMA->gather sync is a 64-thread named
// barrier (bar.sync wm+1, 64) instead of a full-CTA __syncthreads.
// ---------------------------------------------------------------------------
#define BUFW 136                 // [x=64][pk=128 + pad 8]
#define SWS  65                  // sh_w stride
#define K2_SMEM ((64*BUFW + 64*SWS + 64*48 + 64*16 + 64*48 + 64*3 + 64 + 64) * 4)

__global__ __launch_bounds__(256, 2) void k2_fused(const float* __restrict__ node_attr,
                                                   const float* __restrict__ edge_sh,
                                                   const float* __restrict__ b2) {
    extern __shared__ float smem[];
    float* buf   = smem;                        // [x][pk] 64 x 136
    float* sh_w  = buf   + 64 * BUFW;           // [e][x]  64 x 65
    float* sh_c3 = sh_w  + 64 * SWS;            // ALPHA*xs_i        [e][48]
    float* sh_c2 = sh_c3 + 64 * 48;             // ALPHA*dot_i       [e][16]
    float* sh_c4 = sh_c2 + 64 * 16;             // ALPHA*ss*xv[i][m] [e][48]
    float* sh_sv = sh_c4 + 64 * 48;             // [e][3]
    float* sh_ss = sh_sv + 64 * 3;              // [e]
    int*   sh_dst= (int*)(sh_ss + 64);          // [e]

    const int tid  = threadIdx.x;
    const int e0   = blockIdx.x * 64;
    const int wid  = tid >> 5, lane = tid & 31;
    const int wm   = wid & 3,  wn   = wid >> 2;   // warp tile: 16 edges x 32 cols
    const int gg   = lane >> 2, tt  = lane & 3;   // mma lane decomposition
    // gather identity: pair {wm, wm+4} owns edges [wm*16, wm*16+16)
    const int slot = (wn << 5) | lane;            // 0..63 within pair
    const int ge   = wm * 16 + (slot >> 2);       // edge 0..63
    const int gq   = slot & 3;                    // quarter

    // ---- per-edge coefficients (all 256 threads; (ge,gq) is a bijection) ----
    {
        int e = e0 + ge;
        const float* na = node_attr + (size_t)g_src[e] * 96;
        float4 s4 = *(const float4*)(edge_sh + e * 4);
        float ss = s4.x, sv0 = s4.y, sv1 = s4.z, sv2 = s4.w;
        if (gq == 0) {
            sh_dst[ge] = g_dst[e];
            sh_ss[ge]  = ss;
            sh_sv[ge * 3 + 0] = sv0;
            sh_sv[ge * 3 + 1] = sv1;
            sh_sv[ge * 3 + 2] = sv2;
        }
        #pragma unroll
        for (int j = 0; j < 12; ++j) {
            int i = gq * 12 + j;
            sh_c3[ge * 48 + i] = ALPHA * na[i];
        }
        #pragma unroll
        for (int j = 0; j < 4; ++j) {
            int i = gq * 4 + j;
            float a = na[48 + i * 3 + 0];
            float b = na[48 + i * 3 + 1];
            float c = na[48 + i * 3 + 2];
            sh_c2[ge * 16 + i] = ALPHA * INV_SQRT3 * (a * sv0 + b * sv1 + c * sv2);
            sh_c4[ge * 48 + i * 3 + 0] = ALPHA * ss * a;
            sh_c4[ge * 48 + i * 3 + 1] = ALPHA * ss * b;
            sh_c4[ge * 48 + i * 3 + 2] = ALPHA * ss * c;
        }
    }

    // ---- stage h tile into buf (stride 132), extract A frags to regs ----
    #pragma unroll
    for (int it = 0; it < 8; ++it) {
        int p = it * 1024 + tid * 4;
        int e = p >> 7, c = p & 127;
        float4 v = *(const float4*)(g_h + (size_t)(e0 + e) * 128 + c);
        *(float4*)&buf[e * 132 + c] = v;
    }
    __syncthreads();

    unsigned a_r[64];
    {
        const float* hp = buf + (wm * 16 + gg) * 132 + tt;
        #pragma unroll
        for (int ks = 0; ks < 16; ++ks) {
            a_r[ks * 4 + 0] = __float_as_uint(hp[ks * 8]);
            a_r[ks * 4 + 1] = __float_as_uint(hp[ks * 8 + 8 * 132]);
            a_r[ks * 4 + 2] = __float_as_uint(hp[ks * 8 + 4]);
            a_r[ks * 4 + 3] = __float_as_uint(hp[ks * 8 + 8 * 132 + 4]);
        }
    }
    __syncthreads();   // buf free for W2 streaming

    // ---- register message accumulators ----
    float acc_s[12], acc_v[12];
    #pragma unroll
    for (int j = 0; j < 12; ++j) { acc_s[j] = 0.f; acc_v[j] = 0.f; }

    const float* c3row = sh_c3 + ge * 48;
    const float* c2row = sh_c2 + ge * 16;
    const float* c4row = sh_c4 + ge * 48;
    const float* wrow  = sh_w  + ge * SWS;

    // ---- cp.async prefetch of chunk 0 ----
    const unsigned sb = (unsigned)__cvta_generic_to_shared(buf);
    {
        const float* src = g_w2t;
        #pragma unroll
        for (int it = 0; it < 8; ++it) {
            int q = it * 1024 + tid * 4;
            int x = q >> 7, pk = q & 127;
            cp_async16(sb + (unsigned)(x * BUFW + pk) * 4, src + q);
        }
        asm volatile("cp.async.commit_group;\n");
    }

    const unsigned boff = (unsigned)((wn * 32 + gg) * BUFW + tt * 2);
    const int colb0 = wn * 32 + 2 * tt;

    #pragma unroll 1
    for (int cc = 0; cc < 64; ++cc) {
        // bias for this chunk (issues before the barrier; L2-latency hidden)
        float2 bia[4];
        #pragma unroll
        for (int nt = 0; nt < 4; ++nt)
            bia[nt] = *(const float2*)(b2 + cc * 64 + colb0 + nt * 8);

        asm volatile("cp.async.wait_group 0;\n");
        __syncthreads();   // chunk cc resident in buf

        // ---- Phase A: tf32 mma, 64x64 tile; A from regs, B via LDS.64 ----
        float acc[4][4];
        #pragma unroll
        for (int nt = 0; nt < 4; ++nt)
            #pragma unroll
            for (int j = 0; j < 4; ++j) acc[nt][j] = 0.f;

        const float* bbase = buf + boff;
        #pragma unroll
        for (int ks = 0; ks < 16; ++ks) {
            #pragma unroll
            for (int nt = 0; nt < 4; ++nt) {
                uint2 bb = *(const uint2*)(bbase + nt * 8 * BUFW + ks * 8);
                mma_tf32(acc[nt], &a_r[ks * 4], bb);
            }
        }

        // bias + dlrelu + store w tile
        #pragma unroll
        for (int nt = 0; nt < 4; ++nt) {
            int colb = colb0 + nt * 8;
            float z0 = acc[nt][0] + bia[nt].x;
            float z1 = acc[nt][1] + bia[nt].y;
            float z2 = acc[nt][2] + bia[nt].x;
            float z3 = acc[nt][3] + bia[nt].y;
            z0 = (fabsf(z0) <= 10.f) ? z0 : 0.01f * z0;
            z1 = (fabsf(z1) <= 10.f) ? z1 : 0.01f * z1;
            z2 = (fabsf(z2) <= 10.f) ? z2 : 0.01f * z2;
            z3 = (fabsf(z3) <= 10.f) ? z3 : 0.01f * z3;
            sh_w[(wm * 16 + gg)     * SWS + colb]     = z0;
            sh_w[(wm * 16 + gg)     * SWS + colb + 1] = z1;
            sh_w[(wm * 16 + gg + 8) * SWS + colb]     = z2;
            sh_w[(wm * 16 + gg + 8) * SWS + colb + 1] = z3;
        }
        // pair barrier: writers {wm, wm+4} of rows [16wm,16wm+16) == readers
        asm volatile("bar.sync %0, 64;" :: "r"(wm + 1) : "memory");

        // ---- prefetch chunk cc+1 (overlaps gather below) ----
        if (cc < 63) {
            const float* src = g_w2t + (size_t)(cc + 1) * 8192;
            #pragma unroll
            for (int it = 0; it < 8; ++it) {
                int q = it * 1024 + tid * 4;
                int x = q >> 7, pk = q & 127;
                cp_async16(sb + (unsigned)(x * BUFW + pk) * 4, src + q);
            }
            asm volatile("cp.async.commit_group;\n");
        }

        // ---- Phase B: gather into register accumulators ----
        if (cc < 36) {                         // w_ss: col = i*48 + k
            int base = cc * 64;
            int i0   = base / 48;
            int off  = base - i0 * 48;         // 0, 16, 32
            float ssv = sh_ss[ge];
            float ci0 = ssv * c3row[i0];
            float ci1 = (i0 + 1 < 48) ? ssv * c3row[i0 + 1] : 0.f;
            #pragma unroll
            for (int j = 0; j < 12; ++j) {
                int k  = gq * 12 + j;
                int l0 = k - off;
                if (l0 >= 0)      acc_s[j] += ci0 * wrow[l0];
                if (l0 + 48 < 64) acc_s[j] += ci1 * wrow[l0 + 48];
            }
        } else if (cc < 48) {                  // w_vs: col = 2304 + i*48 + k
            int tb  = cc * 64 - 2304;
            int i0  = tb / 48;
            int off = tb - i0 * 48;
            float ci0 = c2row[i0];
            float ci1 = (i0 + 1 < 16) ? c2row[i0 + 1] : 0.f;
            #pragma unroll
            for (int j = 0; j < 12; ++j) {
                int k  = gq * 12 + j;
                int l0 = k - off;
                if (l0 >= 0)      acc_s[j] += ci0 * wrow[l0];
                if (l0 + 48 < 64) acc_s[j] += ci1 * wrow[l0 + 48];
            }
        } else if (cc < 60) {                  // w_sv: col = 3072 + i*16 + k
            int i0 = 4 * (cc - 48);
            float c30 = c3row[i0], c31 = c3row[i0 + 1];
            float c32 = c3row[i0 + 2], c33 = c3row[i0 + 3];
            float sv0 = sh_sv[ge * 3], sv1 = sh_sv[ge * 3 + 1], sv2 = sh_sv[ge * 3 + 2];
            #pragma unroll
            for (int kk = 0; kk < 4; ++kk) {
                int k = gq * 4 + kk;
                float s = c30 * wrow[k] + c31 * wrow[16 + k]
                        + c32 * wrow[32 + k] + c33 * wrow[48 + k];
                acc_v[kk * 3 + 0] += s * sv0;
                acc_v[kk * 3 + 1] += s * sv1;
                acc_v[kk * 3 + 2] += s * sv2;
            }
        } else {                               // w_vv: col = 3840 + i*16 + k
            int i0 = 4 * (cc - 60);
            const float* c4p = c4row + i0 * 3;  // 12 coeffs
            #pragma unroll
            for (int kk = 0; kk < 4; ++kk) {
                int k = gq * 4 + kk;
                float w0 = wrow[k],      w1 = wrow[16 + k];
                float w2 = wrow[32 + k], w3 = wrow[48 + k];
                acc_v[kk * 3 + 0] += c4p[0] * w0 + c4p[3] * w1 + c4p[6] * w2 + c4p[9]  * w3;
                acc_v[kk * 3 + 1] += c4p[1] * w0 + c4p[4] * w1 + c4p[7] * w2 + c4p[10] * w3;
                acc_v[kk * 3 + 2] += c4p[2] * w0 + c4p[5] * w1 + c4p[8] * w2 + c4p[11] * w3;
            }
        }
    }

    // ---- writeout: 24 global atomics per thread ----
    int dst = sh_dst[ge];
    float* gp = g_acc + (size_t)dst * 96;
    #pragma unroll
    for (int j = 0; j < 12; ++j) atomicAdd(gp + gq * 12 + j, acc_s[j]);
    #pragma unroll
    for (int j = 0; j < 12; ++j) atomicAdd(gp + 48 + gq * 12 + j, acc_v[j]);
}

// ---------------------------------------------------------------------------
// K3: batchnorm statistics
// ---------------------------------------------------------------------------
__global__ __launch_bounds__(256) void k3_stats(const float* __restrict__ bnw,
                                                const float* __restrict__ bnb) {
    __shared__ double rs[256], rs2[256];
    int b = blockIdx.x, tid = threadIdx.x;
    double s = 0.0, s2 = 0.0;
    if (b < 48) {
        for (int n = tid; n < NN; n += 256) {
            float x = g_acc[(size_t)n * 96 + b];
            s  += (double)x;
            s2 += (double)x * (double)x;
        }
    } else {
        int j = b - 48;
        for (int n = tid; n < NN; n += 256) {
            const float* p = &g_acc[(size_t)n * 96 + 48 + j * 3];
            s2 += (double)p[0] * p[0] + (double)p[1] * p[1] + (double)p[2] * p[2];
        }
    }
    rs[tid] = s; rs2[tid] = s2;
    __syncthreads();
    for (int st = 128; st > 0; st >>= 1) {
        if (tid < st) { rs[tid] += rs[tid + st]; rs2[tid] += rs2[tid + st]; }
        __syncthreads();
    }
    if (tid == 0) {
        if (b < 48) {
            double mean = rs[0] / (double)NN;
            double var  = rs2[0] / (double)NN - mean * mean;
            double scale = (double)bnw[b] / sqrt(var + 1e-5);
            g_scale[b] = (float)scale;
            g_shift[b] = bnb[b] - (float)(mean * scale);
        } else {
            double vn = rs2[0] / ((double)NN * 3.0);
            g_scale[b] = (float)((double)bnw[b] / sqrt(vn + 1e-5));
        }
    }
}

// ---------------------------------------------------------------------------
// K4: apply normalization -> d_out
// ---------------------------------------------------------------------------
__global__ void k4_apply(float* __restrict__ out) {
    int idx = blockIdx.x * 256 + threadIdx.x;
    float x = g_acc[idx];
    int f = idx % 96;
    float r;
    if (f < 48) r = x * g_scale[f] + g_shift[f];
    else        r = x * g_scale[48 + (f - 48) / 3];
    out[idx] = r;
}

// ---------------------------------------------------------------------------
extern "C" void kernel_launch(void* const* d_in, const int* in_sizes, int n_in,
                              void* d_out, int out_size) {
    const float* node_attr = (const float*)d_in[0];
    const int*   eidx      = (const int*)d_in[1];   // int32 OR int64 (auto-detected)
    const float* edge_attr = (const float*)d_in[2];
    const float* edge_sh   = (const float*)d_in[3];
    const float* W1        = (const float*)d_in[4];
    const float* b1        = (const float*)d_in[5];
    const float* W2        = (const float*)d_in[6];
    const float* b2        = (const float*)d_in[7];
    const float* bnw       = (const float*)d_in[8];
    const float* bnb       = (const float*)d_in[9];
    float*       out       = (float*)d_out;

    cudaFuncSetAttribute(k1_gemm,  cudaFuncAttributeMaxDynamicSharedMemorySize, K1_SMEM);
    cudaFuncSetAttribute(k2_fused, cudaFuncAttributeMaxDynamicSharedMemorySize, K2_SMEM);

    k_detect<<<1, 256>>>(eidx);
    k_unpack<<<EE / 256, 256>>>(eidx);
    k_w2t   <<<64, 256>>>(W2);
    k0_init <<<(NN * 96) / 256, 256>>>(node_attr);
    k1_gemm <<<EE / 64, 256, K1_SMEM>>>(edge_attr, W1, b1);
    k2_fused<<<EE / 64, 256, K2_SMEM>>>(node_attr, edge_sh, b2);
    k3_stats<<<64, 256>>>(bnw, bnb);
    k4_apply<<<(NN * 96) / 256, 256>>>(out);
}

// round 15
// speedup vs baseline: 1.0726x; 1.0726x over previous
#include <cuda_runtime.h>
#include <cuda_bf16.h>
#include <math.h>

// Problem constants
#define NN     4096
#define EE     32768
#define ALPHA  0.125f
#define INV_SQRT3 0.57735026918962576f

// Scratch (device globals: no runtime allocation allowed)
__device__ float g_h[(size_t)EE * 128];     // 16 MB: relu(edge_attr @ W1 + b1), tf32-rounded
__device__ float g_w2t[64 * 8192];          // 2 MB: W2 repacked per-chunk [x][pk], tf32-rounded
__device__ float g_acc[(size_t)NN * 96];    // residual + scattered messages
__device__ float g_scale[64];
__device__ float g_shift[48];
__device__ int   g_src[EE];
__device__ int   g_dst[EE];
__device__ int   g_i64;

// ---------------------------------------------------------------------------
// helpers
// ---------------------------------------------------------------------------
__device__ __forceinline__ float to_tf32(float x) {
    float r; asm("cvt.rna.tf32.f32 %0, %1;" : "=f"(r) : "f"(x)); return r;
}
__device__ __forceinline__ void mma_tf32(float* d, const unsigned* a, uint2 b) {
    asm volatile("mma.sync.aligned.m16n8k8.row.col.f32.tf32.tf32.f32 "
                 "{%0,%1,%2,%3}, {%4,%5,%6,%7}, {%8,%9}, {%0,%1,%2,%3};\n"
                 : "+f"(d[0]), "+f"(d[1]), "+f"(d[2]), "+f"(d[3])
                 : "r"(a[0]), "r"(a[1]), "r"(a[2]), "r"(a[3]),
                   "r"(b.x), "r"(b.y));
}
__device__ __forceinline__ void cp_async16(unsigned smem, const void* gmem) {
    asm volatile("cp.async.cg.shared.global [%0], [%1], 16;\n" :: "r"(smem), "l"(gmem));
}

// ---------------------------------------------------------------------------
// K-1a: detect edge_index dtype (int32 vs int64 little-endian)
// ---------------------------------------------------------------------------
__global__ void k_detect(const int* __restrict__ buf) {
    __shared__ int nz;
    if (threadIdx.x == 0) nz = 0;
    __syncthreads();
    int c = 0;
    for (int i = threadIdx.x; i < 2048; i += 256)
        if (buf[2 * i + 1] != 0) c++;
    if (c) atomicAdd(&nz, c);
    __syncthreads();
    if (threadIdx.x == 0) g_i64 = (nz == 0) ? 1 : 0;
}

// K-1b: unpack edge indices into int32 arrays (clamped defensively)
__global__ void k_unpack(const int* __restrict__ buf) {
    int e = blockIdx.x * 256 + threadIdx.x;
    int i64 = g_i64;
    int s = i64 ? buf[2 * e]          : buf[e];
    int d = i64 ? buf[2 * EE + 2 * e] : buf[EE + e];
    g_src[e] = min(max(s, 0), NN - 1);
    g_dst[e] = min(max(d, 0), NN - 1);
}

// ---------------------------------------------------------------------------
// K0: init accumulator with node_attr (residual)
// ---------------------------------------------------------------------------
__global__ void k0_init(const float* __restrict__ node_attr) {
    int idx = blockIdx.x * 256 + threadIdx.x;
    g_acc[idx] = node_attr[idx];
}

// ---------------------------------------------------------------------------
// K_w2t: one-time repack of W2 (128 x 4096) into per-chunk [x=64][pk=128]
// blocks, tf32-rounded.  pk(k) = (k>>3)*8 + (k&3)*2 + ((k>>2)&1) makes the
// two k-halves of each tf32 B-fragment adjacent -> LDS.64 in K2 mainloop.
// ---------------------------------------------------------------------------
__global__ __launch_bounds__(256) void k_w2t(const float* __restrict__ W2) {
    __shared__ float sm[128 * 69];   // [k][x] stride 69
    const int cc = blockIdx.x, tid = threadIdx.x;
    #pragma unroll
    for (int it = 0; it < 8; ++it) {
        int p = it * 1024 + tid * 4;
        int r = p >> 6, x = p & 63;
        float4 v = *(const float4*)(W2 + (size_t)r * 4096 + cc * 64 + x);
        sm[r * 69 + x + 0] = v.x;
        sm[r * 69 + x + 1] = v.y;
        sm[r * 69 + x + 2] = v.z;
        sm[r * 69 + x + 3] = v.w;
    }
    __syncthreads();
    #pragma unroll
    for (int it = 0; it < 8; ++it) {
        int q = it * 1024 + tid * 4;
        int x = q >> 7, pk0 = q & 127;
        float4 o;
        float* op = (float*)&o;
        #pragma unroll
        for (int l = 0; l < 4; ++l) {
            int pk = pk0 + l;
            int k = (pk >> 3) * 8 + (pk & 1) * 4 + ((pk & 7) >> 1);
            op[l] = to_tf32(sm[k * 69 + x]);
        }
        *(float4*)(g_w2t + (size_t)cc * 8192 + q) = o;
    }
}

// ---------------------------------------------------------------------------
// K1: h = relu(edge_attr @ W1 + b1)   (E x 128 x 128) — fp32 FFMA,
//     output tf32-rounded.  smem 100.4 KB x 2 CTAs = 200.7 KB <= 228 KB,
//     so 2 CTAs/SM (16 warps) for latency hiding.
// ---------------------------------------------------------------------------
#define K1_SMEM ((128*68 + 128*128) * 4)
__global__ __launch_bounds__(256, 2) void k1_gemm(const float* __restrict__ ea,
                                                  const float* __restrict__ W1,
                                                  const float* __restrict__ b1) {
    extern __shared__ float smem[];
    float* sh_aT = smem;              // [c][e], stride 68
    float* sh_w1 = smem + 128 * 68;   // [c][o], stride 128

    const int tid = threadIdx.x;
    const int e0  = blockIdx.x * 64;
    const int ty  = tid >> 4, tx = tid & 15;

    #pragma unroll
    for (int it = 0; it < 8; ++it) {
        int p = it * 1024 + tid * 4;
        int e = p >> 7, c = p & 127;
        float4 v = *(const float4*)(ea + (size_t)(e0 + e) * 128 + c);
        sh_aT[(c + 0) * 68 + e] = v.x;
        sh_aT[(c + 1) * 68 + e] = v.y;
        sh_aT[(c + 2) * 68 + e] = v.z;
        sh_aT[(c + 3) * 68 + e] = v.w;
    }
    #pragma unroll
    for (int it = 0; it < 16; ++it) {
        int p = it * 1024 + tid * 4;
        *(float4*)&sh_w1[p] = *(const float4*)(W1 + p);
    }
    __syncthreads();

    float acc[4][8];
    #pragma unroll
    for (int i = 0; i < 4; ++i)
        #pragma unroll
        for (int j = 0; j < 8; ++j) acc[i][j] = 0.f;

    #pragma unroll 4
    for (int c = 0; c < 128; ++c) {
        float4 a  = *(const float4*)&sh_aT[c * 68 + ty * 4];
        float4 w0 = *(const float4*)&sh_w1[c * 128 + tx * 8];
        float4 w1v= *(const float4*)&sh_w1[c * 128 + tx * 8 + 4];
        const float av[4] = {a.x, a.y, a.z, a.w};
        const float bv[8] = {w0.x, w0.y, w0.z, w0.w, w1v.x, w1v.y, w1v.z, w1v.w};
        #pragma unroll
        for (int i = 0; i < 4; ++i)
            #pragma unroll
            for (int j = 0; j < 8; ++j) acc[i][j] += av[i] * bv[j];
    }

    float4 bb0 = *(const float4*)(b1 + tx * 8);
    float4 bb1 = *(const float4*)(b1 + tx * 8 + 4);
    const float bias[8] = {bb0.x, bb0.y, bb0.z, bb0.w, bb1.x, bb1.y, bb1.z, bb1.w};
    #pragma unroll
    for (int i = 0; i < 4; ++i) {
        size_t row = (size_t)(e0 + ty * 4 + i) * 128 + tx * 8;
        float4 o0, o1;
        o0.x = to_tf32(fmaxf(acc[i][0] + bias[0], 0.f));
        o0.y = to_tf32(fmaxf(acc[i][1] + bias[1], 0.f));
        o0.z = to_tf32(fmaxf(acc[i][2] + bias[2], 0.f));
        o0.w = to_tf32(fmaxf(acc[i][3] + bias[3], 0.f));
        o1.x = to_tf32(fmaxf(acc[i][4] + bias[4], 0.f));
        o1.y = to_tf32(fmaxf(acc[i][5] + bias[5], 0.f));
        o1.z = to_tf32(fmaxf(acc[i][6] + bias[6], 0.f));
        o1.w = to_tf32(fmaxf(acc[i][7] + bias[7], 0.f));
        *(float4*)(g_h + row)     = o0;
        *(float4*)(g_h + row + 4) = o1;
    }
}

// ---------------------------------------------------------------------------
// K2: fused  w = dlrelu(h @ W2 + b2)  (tf32 mma)  +  per-edge contraction.
// A-fragments hoisted to registers; W2 streamed via cp.async into a SINGLE
// smem buffer (prefetch of chunk cc+1 issued before the gather phase of cc,
// so its latency hides under the gather + the co-resident CTA).
// smem = 81.4 KB -> 2 CTAs/SM (16 warps) for latency hiding.
// BUFW = 136 (== 8 mod 32): B-fragment LDS.64 start banks gg*8+tt*2 put
// exactly 2 lanes on each bank-pair -> conflict-free (2-phase minimum).
// CTA: 64 edges, 64-col chunks, 256 threads (8 warps: 4m x 2n).
// ---------------------------------------------------------------------------
#define BUFW 136                 // [x=64][pk=128 + pad 8]
#define SWS  65                  // sh_w stride
#define K2_SMEM ((64*BUFW + 64*SWS + 64*48 + 64*16 + 64*48 + 64*3 + 64 + 64) * 4)

__global__ __launch_bounds__(256, 2) void k2_fused(const float* __restrict__ node_attr,
                                                   const float* __restrict__ edge_sh,
                                                   const float* __restrict__ b2) {
    extern __shared__ float smem[];
    float* buf   = smem;                        // [x][pk] 64 x 136
    float* sh_w  = buf   + 64 * BUFW;           // [e][x]  64 x 65
    float* sh_c3 = sh_w  + 64 * SWS;            // ALPHA*xs_i        [e][48]
    float* sh_c2 = sh_c3 + 64 * 48;             // ALPHA*dot_i       [e][16]
    float* sh_c4 = sh_c2 + 64 * 16;             // ALPHA*ss*xv[i][m] [e][48]
    float* sh_sv = sh_c4 + 64 * 48;             // [e][3]
    float* sh_ss = sh_sv + 64 * 3;              // [e]
    int*   sh_dst= (int*)(sh_ss + 64);          // [e]

    const int tid  = threadIdx.x;
    const int e0   = blockIdx.x * 64;
    const int wid  = tid >> 5, lane = tid & 31;
    const int wm   = wid & 3,  wn   = wid >> 2;   // warp tile: 16 edges x 32 cols
    const int gg   = lane >> 2, tt  = lane & 3;   // mma lane decomposition
    const int ge   = tid >> 2;                    // gather edge 0..63
    const int gq   = tid & 3;                     // gather quarter

    // ---- per-edge coefficients (all 256 threads) ----
    {
        int e = e0 + ge;
        const float* na = node_attr + (size_t)g_src[e] * 96;
        float4 s4 = *(const float4*)(edge_sh + e * 4);
        float ss = s4.x, sv0 = s4.y, sv1 = s4.z, sv2 = s4.w;
        if (gq == 0) {
            sh_dst[ge] = g_dst[e];
            sh_ss[ge]  = ss;
            sh_sv[ge * 3 + 0] = sv0;
            sh_sv[ge * 3 + 1] = sv1;
            sh_sv[ge * 3 + 2] = sv2;
        }
        #pragma unroll
        for (int j = 0; j < 12; ++j) {
            int i = gq * 12 + j;
            sh_c3[ge * 48 + i] = ALPHA * na[i];
        }
        #pragma unroll
        for (int j = 0; j < 4; ++j) {
            int i = gq * 4 + j;
            float a = na[48 + i * 3 + 0];
            float b = na[48 + i * 3 + 1];
            float c = na[48 + i * 3 + 2];
            sh_c2[ge * 16 + i] = ALPHA * INV_SQRT3 * (a * sv0 + b * sv1 + c * sv2);
            sh_c4[ge * 48 + i * 3 + 0] = ALPHA * ss * a;
            sh_c4[ge * 48 + i * 3 + 1] = ALPHA * ss * b;
            sh_c4[ge * 48 + i * 3 + 2] = ALPHA * ss * c;
        }
    }

    // ---- stage h tile into buf (stride 132), extract A frags to regs ----
    #pragma unroll
    for (int it = 0; it < 8; ++it) {
        int p = it * 1024 + tid * 4;
        int e = p >> 7, c = p & 127;
        float4 v = *(const float4*)(g_h + (size_t)(e0 + e) * 128 + c);
        *(float4*)&buf[e * 132 + c] = v;
    }
    __syncthreads();

    unsigned a_r[64];
    {
        const float* hp = buf + (wm * 16 + gg) * 132 + tt;
        #pragma unroll
        for (int ks = 0; ks < 16; ++ks) {
            a_r[ks * 4 + 0] = __float_as_uint(hp[ks * 8]);
            a_r[ks * 4 + 1] = __float_as_uint(hp[ks * 8 + 8 * 132]);
            a_r[ks * 4 + 2] = __float_as_uint(hp[ks * 8 + 4]);
            a_r[ks * 4 + 3] = __float_as_uint(hp[ks * 8 + 8 * 132 + 4]);
        }
    }
    __syncthreads();   // buf free for W2 streaming

    // ---- register message accumulators ----
    float acc_s[12], acc_v[12];
    #pragma unroll
    for (int j = 0; j < 12; ++j) { acc_s[j] = 0.f; acc_v[j] = 0.f; }

    const float* c3row = sh_c3 + ge * 48;
    const float* c2row = sh_c2 + ge * 16;
    const float* c4row = sh_c4 + ge * 48;
    const float* wrow  = sh_w  + ge * SWS;

    // ---- cp.async prefetch of chunk 0 ----
    const unsigned sb = (unsigned)__cvta_generic_to_shared(buf);
    {
        const float* src = g_w2t;
        #pragma unroll
        for (int it = 0; it < 8; ++it) {
            int q = it * 1024 + tid * 4;
            int x = q >> 7, pk = q & 127;
            cp_async16(sb + (unsigned)(x * BUFW + pk) * 4, src + q);
        }
        asm volatile("cp.async.commit_group;\n");
    }

    const unsigned boff = (unsigned)((wn * 32 + gg) * BUFW + tt * 2);

    #pragma unroll 1
    for (int cc = 0; cc < 64; ++cc) {
        asm volatile("cp.async.wait_group 0;\n");
        __syncthreads();   // chunk cc resident in buf

        // ---- Phase A: tf32 mma, 64x64 tile; A from regs, B via LDS.64 ----
        float acc[4][4];
        #pragma unroll
        for (int nt = 0; nt < 4; ++nt)
            #pragma unroll
            for (int j = 0; j < 4; ++j) acc[nt][j] = 0.f;

        const float* bbase = buf + boff;
        #pragma unroll
        for (int ks = 0; ks < 16; ++ks) {
            #pragma unroll
            for (int nt = 0; nt < 4; ++nt) {
                uint2 bb = *(const uint2*)(bbase + nt * 8 * BUFW + ks * 8);
                mma_tf32(acc[nt], &a_r[ks * 4], bb);
            }
        }

        // bias + dlrelu + store w tile
        #pragma unroll
        for (int nt = 0; nt < 4; ++nt) {
            int colb = wn * 32 + nt * 8 + 2 * tt;
            float2 bia = *(const float2*)(b2 + cc * 64 + colb);
            float z0 = acc[nt][0] + bia.x;
            float z1 = acc[nt][1] + bia.y;
            float z2 = acc[nt][2] + bia.x;
            float z3 = acc[nt][3] + bia.y;
            z0 = (fabsf(z0) <= 10.f) ? z0 : 0.01f * z0;
            z1 = (fabsf(z1) <= 10.f) ? z1 : 0.01f * z1;
            z2 = (fabsf(z2) <= 10.f) ? z2 : 0.01f * z2;
            z3 = (fabsf(z3) <= 10.f) ? z3 : 0.01f * z3;
            sh_w[(wm * 16 + gg)     * SWS + colb]     = z0;
            sh_w[(wm * 16 + gg)     * SWS + colb + 1] = z1;
            sh_w[(wm * 16 + gg + 8) * SWS + colb]     = z2;
            sh_w[(wm * 16 + gg + 8) * SWS + colb + 1] = z3;
        }
        __syncthreads();   // w tile visible; all mma reads of buf complete

        // ---- prefetch chunk cc+1 (overlaps gather below) ----
        if (cc < 63) {
            const float* src = g_w2t + (size_t)(cc + 1) * 8192;
            #pragma unroll
            for (int it = 0; it < 8; ++it) {
                int q = it * 1024 + tid * 4;
                int x = q >> 7, pk = q & 127;
                cp_async16(sb + (unsigned)(x * BUFW + pk) * 4, src + q);
            }
            asm volatile("cp.async.commit_group;\n");
        }

        // ---- Phase B: gather into register accumulators ----
        if (cc < 36) {                         // w_ss: col = i*48 + k
            int base = cc * 64;
            int i0   = base / 48;
            int off  = base - i0 * 48;         // 0, 16, 32
            float ssv = sh_ss[ge];
            float ci0 = ssv * c3row[i0];
            float ci1 = (i0 + 1 < 48) ? ssv * c3row[i0 + 1] : 0.f;
            #pragma unroll
            for (int j = 0; j < 12; ++j) {
                int k  = gq * 12 + j;
                int l0 = k - off;
                if (l0 >= 0)      acc_s[j] += ci0 * wrow[l0];
                if (l0 + 48 < 64) acc_s[j] += ci1 * wrow[l0 + 48];
            }
        } else if (cc < 48) {                  // w_vs: col = 2304 + i*48 + k
            int tb  = cc * 64 - 2304;
            int i0  = tb / 48;
            int off = tb - i0 * 48;
            float ci0 = c2row[i0];
            float ci1 = (i0 + 1 < 16) ? c2row[i0 + 1] : 0.f;
            #pragma unroll
            for (int j = 0; j < 12; ++j) {
                int k  = gq * 12 + j;
                int l0 = k - off;
                if (l0 >= 0)      acc_s[j] += ci0 * wrow[l0];
                if (l0 + 48 < 64) acc_s[j] += ci1 * wrow[l0 + 48];
            }
        } else if (cc < 60) {                  // w_sv: col = 3072 + i*16 + k
            int i0 = 4 * (cc - 48);
            float c30 = c3row[i0], c31 = c3row[i0 + 1];
            float c32 = c3row[i0 + 2], c33 = c3row[i0 + 3];
            float sv0 = sh_sv[ge * 3], sv1 = sh_sv[ge * 3 + 1], sv2 = sh_sv[ge * 3 + 2];
            #pragma unroll
            for (int kk = 0; kk < 4; ++kk) {
                int k = gq * 4 + kk;
                float s = c30 * wrow[k] + c31 * wrow[16 + k]
                        + c32 * wrow[32 + k] + c33 * wrow[48 + k];
                acc_v[kk * 3 + 0] += s * sv0;
                acc_v[kk * 3 + 1] += s * sv1;
                acc_v[kk * 3 + 2] += s * sv2;
            }
        } else {                               // w_vv: col = 3840 + i*16 + k
            int i0 = 4 * (cc - 60);
            const float* c4p = c4row + i0 * 3;  // 12 coeffs
            #pragma unroll
            for (int kk = 0; kk < 4; ++kk) {
                int k = gq * 4 + kk;
                float w0 = wrow[k],      w1 = wrow[16 + k];
                float w2 = wrow[32 + k], w3 = wrow[48 + k];
                acc_v[kk * 3 + 0] += c4p[0] * w0 + c4p[3] * w1 + c4p[6] * w2 + c4p[9]  * w3;
                acc_v[kk * 3 + 1] += c4p[1] * w0 + c4p[4] * w1 + c4p[7] * w2 + c4p[10] * w3;
                acc_v[kk * 3 + 2] += c4p[2] * w0 + c4p[5] * w1 + c4p[8] * w2 + c4p[11] * w3;
            }
        }
    }

    // ---- writeout: 24 global atomics per thread ----
    int dst = sh_dst[ge];
    float* gp = g_acc + (size_t)dst * 96;
    #pragma unroll
    for (int j = 0; j < 12; ++j) atomicAdd(gp + gq * 12 + j, acc_s[j]);
    #pragma unroll
    for (int j = 0; j < 12; ++j) atomicAdd(gp + 48 + gq * 12 + j, acc_v[j]);
}

// ---------------------------------------------------------------------------
// K3: batchnorm statistics
// ---------------------------------------------------------------------------
__global__ __launch_bounds__(256) void k3_stats(const float* __restrict__ bnw,
                                                const float* __restrict__ bnb) {
    __shared__ double rs[256], rs2[256];
    int b = blockIdx.x, tid = threadIdx.x;
    double s = 0.0, s2 = 0.0;
    if (b < 48) {
        for (int n = tid; n < NN; n += 256) {
            float x = g_acc[(size_t)n * 96 + b];
            s  += (double)x;
            s2 += (double)x * (double)x;
        }
    } else {
        int j = b - 48;
        for (int n = tid; n < NN; n += 256) {
            const float* p = &g_acc[(size_t)n * 96 + 48 + j * 3];
            s2 += (double)p[0] * p[0] + (double)p[1] * p[1] + (double)p[2] * p[2];
        }
    }
    rs[tid] = s; rs2[tid] = s2;
    __syncthreads();
    for (int st = 128; st > 0; st >>= 1) {
        if (tid < st) { rs[tid] += rs[tid + st]; rs2[tid] += rs2[tid + st]; }
        __syncthreads();
    }
    if (tid == 0) {
        if (b < 48) {
            double mean = rs[0] / (double)NN;
            double var  = rs2[0] / (double)NN - mean * mean;
            double scale = (double)bnw[b] / sqrt(var + 1e-5);
            g_scale[b] = (float)scale;
            g_shift[b] = bnb[b] - (float)(mean * scale);
        } else {
            double vn = rs2[0] / ((double)NN * 3.0);
            g_scale[b] = (float)((double)bnw[b] / sqrt(vn + 1e-5));
        }
    }
}

// ---------------------------------------------------------------------------
// K4: apply normalization -> d_out
// ---------------------------------------------------------------------------
__global__ void k4_apply(float* __restrict__ out) {
    int idx = blockIdx.x * 256 + threadIdx.x;
    float x = g_acc[idx];
    int f = idx % 96;
    float r;
    if (f < 48) r = x * g_scale[f] + g_shift[f];
    else        r = x * g_scale[48 + (f - 48) / 3];
    out[idx] = r;
}

// ---------------------------------------------------------------------------
extern "C" void kernel_launch(void* const* d_in, const int* in_sizes, int n_in,
                              void* d_out, int out_size) {
    const float* node_attr = (const float*)d_in[0];
    const int*   eidx      = (const int*)d_in[1];   // int32 OR int64 (auto-detected)
    const float* edge_attr = (const float*)d_in[2];
    const float* edge_sh   = (const float*)d_in[3];
    const float* W1        = (const float*)d_in[4];
    const float* b1        = (const float*)d_in[5];
    const float* W2        = (const float*)d_in[6];
    const float* b2        = (const float*)d_in[7];
    const float* bnw       = (const float*)d_in[8];
    const float* bnb       = (const float*)d_in[9];
    float*       out       = (float*)d_out;

    cudaFuncSetAttribute(k1_gemm,  cudaFuncAttributeMaxDynamicSharedMemorySize, K1_SMEM);
    cudaFuncSetAttribute(k2_fused, cudaFuncAttributeMaxDynamicSharedMemorySize, K2_SMEM);

    k_detect<<<1, 256>>>(eidx);
    k_unpack<<<EE / 256, 256>>>(eidx);
    k_w2t   <<<64, 256>>>(W2);
    k0_init <<<(NN * 96) / 256, 256>>>(node_attr);
    k1_gemm <<<EE / 64, 256, K1_SMEM>>>(edge_attr, W1, b1);
    k2_fused<<<EE / 64, 256, K2_SMEM>>>(node_attr, edge_sh, b2);
    k3_stats<<<64, 256>>>(bnw, bnb);
    k4_apply<<<(NN * 96) / 256, 256>>>(out);
}

// round 16
// speedup vs baseline: 1.1778x; 1.0980x over previous
#include <cuda_runtime.h>
#include <cuda_bf16.h>
#include <math.h>

// Problem constants
#define NN     4096
#define EE     32768
#define ALPHA  0.125f
#define INV_SQRT3 0.57735026918962576f

// Scratch (device globals: no runtime allocation allowed)
__device__ float g_h[(size_t)EE * 128];     // 16 MB: relu(edge_attr @ W1 + b1), tf32-rounded
__device__ float g_w2t[64 * 8192];          // 2 MB: W2 repacked per-chunk [x][pk], tf32-rounded
__device__ float g_w1t[128 * 128];          // 64 KB: W1 repacked [o][pk], tf32-rounded
__device__ float g_acc[(size_t)NN * 96];    // residual + scattered messages
__device__ float g_scale[64];
__device__ float g_shift[48];
__device__ int   g_src[EE];
__device__ int   g_dst[EE];

// ---------------------------------------------------------------------------
// helpers
// ---------------------------------------------------------------------------
__device__ __forceinline__ float to_tf32(float x) {
    float r; asm("cvt.rna.tf32.f32 %0, %1;" : "=f"(r) : "f"(x)); return r;
}
__device__ __forceinline__ void mma_tf32(float* d, const unsigned* a, uint2 b) {
    asm volatile("mma.sync.aligned.m16n8k8.row.col.f32.tf32.tf32.f32 "
                 "{%0,%1,%2,%3}, {%4,%5,%6,%7}, {%8,%9}, {%0,%1,%2,%3};\n"
                 : "+f"(d[0]), "+f"(d[1]), "+f"(d[2]), "+f"(d[3])
                 : "r"(a[0]), "r"(a[1]), "r"(a[2]), "r"(a[3]),
                   "r"(b.x), "r"(b.y));
}
__device__ __forceinline__ void cp_async16(unsigned smem, const void* gmem) {
    asm volatile("cp.async.cg.shared.global [%0], [%1], 16;\n" :: "r"(smem), "l"(gmem));
}
// forward pk mapping: pk(k) = (k>>3)*8 + (k&3)*2 + ((k>>2)&1)
__device__ __forceinline__ int pk_of_k(int k) {
    return ((k >> 3) << 3) | ((k & 3) << 1) | ((k >> 2) & 1);
}

// ---------------------------------------------------------------------------
// K_pre: fused prologue.
//   blocks [0,128):     edge_index dtype detect (per-block) + unpack
//   blocks [128,1664):  g_acc = node_attr (residual init)
//   blocks [1664,1728): W1 repack into g_w1t [o=128][pk=128], tf32-rounded
// ---------------------------------------------------------------------------
__global__ __launch_bounds__(256) void k_pre(const int* __restrict__ buf,
                                             const float* __restrict__ node_attr,
                                             const float* __restrict__ W1) {
    int b = blockIdx.x;
    if (b < 128) {
        __shared__ int nz;
        if (threadIdx.x == 0) nz = 0;
        __syncthreads();
        int c = 0;
        for (int i = threadIdx.x; i < 2048; i += 256)
            if (buf[2 * i + 1] != 0) c++;
        if (c) atomicAdd(&nz, c);
        __syncthreads();
        int i64 = (nz == 0) ? 1 : 0;
        int e = b * 256 + threadIdx.x;
        int s = i64 ? buf[2 * e]          : buf[e];
        int d = i64 ? buf[2 * EE + 2 * e] : buf[EE + e];
        g_src[e] = min(max(s, 0), NN - 1);
        g_dst[e] = min(max(d, 0), NN - 1);
    } else if (b < 1664) {
        int idx = (b - 128) * 256 + threadIdx.x;
        g_acc[idx] = node_attr[idx];
    } else {
        int idx = (b - 1664) * 256 + threadIdx.x;   // [0, 16384)
        int cc = idx >> 7, o = idx & 127;           // W1[cc][o], coalesced read
        g_w1t[o * 128 + pk_of_k(cc)] = to_tf32(W1[idx]);
    }
}

// ---------------------------------------------------------------------------
// K_w2t: one-time repack of W2 (128 x 4096) into per-chunk [x=64][pk=128]
// blocks, tf32-rounded.  pk(k) makes the two k-halves of each tf32
// B-fragment adjacent -> LDS.64 in the mma mainloops.
// ---------------------------------------------------------------------------
__global__ __launch_bounds__(256) void k_w2t(const float* __restrict__ W2) {
    __shared__ float sm[128 * 69];   // [k][x] stride 69
    const int cc = blockIdx.x, tid = threadIdx.x;
    #pragma unroll
    for (int it = 0; it < 8; ++it) {
        int p = it * 1024 + tid * 4;
        int r = p >> 6, x = p & 63;
        float4 v = *(const float4*)(W2 + (size_t)r * 4096 + cc * 64 + x);
        sm[r * 69 + x + 0] = v.x;
        sm[r * 69 + x + 1] = v.y;
        sm[r * 69 + x + 2] = v.z;
        sm[r * 69 + x + 3] = v.w;
    }
    __syncthreads();
    #pragma unroll
    for (int it = 0; it < 8; ++it) {
        int q = it * 1024 + tid * 4;
        int x = q >> 7, pk0 = q & 127;
        float4 o;
        float* op = (float*)&o;
        #pragma unroll
        for (int l = 0; l < 4; ++l) {
            int pk = pk0 + l;
            int k = (pk >> 3) * 8 + (pk & 1) * 4 + ((pk & 7) >> 1);
            op[l] = to_tf32(sm[k * 69 + x]);
        }
        *(float4*)(g_w2t + (size_t)cc * 8192 + q) = o;
    }
}

// ---------------------------------------------------------------------------
// K1: h = relu(edge_attr @ W1 + b1)  (E x 128 x 128) — tf32 tensor cores.
// CTA: 64 edges, 256 threads (8 warps: 4m x 2n, warp tile m16 x n64).
// Stage edge_attr tile into smem (tf32-rounded), hoist A-frags to regs,
// then cp.async the pre-packed W1 into the SAME buffer and run 1024 mma.
// smem 68 KB -> 2 CTAs/SM.
// ---------------------------------------------------------------------------
#define BUFW 136
#define K1_SMEM (128 * BUFW * 4)
__global__ __launch_bounds__(256, 2) void k1_gemm(const float* __restrict__ ea,
                                                  const float* __restrict__ b1) {
    extern __shared__ float smem[];
    float* buf = smem;   // staging [e=64][c] stride 132, then W1 [x=128][pk] stride 136

    const int tid = threadIdx.x;
    const int e0  = blockIdx.x * 64;
    const int wid = tid >> 5, lane = tid & 31;
    const int wm  = wid & 3,  wn   = wid >> 2;
    const int gg  = lane >> 2, tt  = lane & 3;

    // stage edge_attr tile (tf32-rounded)
    #pragma unroll
    for (int it = 0; it < 8; ++it) {
        int p = it * 1024 + tid * 4;
        int e = p >> 7, c = p & 127;
        float4 v = *(const float4*)(ea + (size_t)(e0 + e) * 128 + c);
        float* dp = &buf[e * 132 + c];
        dp[0] = to_tf32(v.x);
        dp[1] = to_tf32(v.y);
        dp[2] = to_tf32(v.z);
        dp[3] = to_tf32(v.w);
    }
    __syncthreads();

    unsigned a_r[64];
    {
        const float* hp = buf + (wm * 16 + gg) * 132 + tt;
        #pragma unroll
        for (int ks = 0; ks < 16; ++ks) {
            a_r[ks * 4 + 0] = __float_as_uint(hp[ks * 8]);
            a_r[ks * 4 + 1] = __float_as_uint(hp[ks * 8 + 8 * 132]);
            a_r[ks * 4 + 2] = __float_as_uint(hp[ks * 8 + 4]);
            a_r[ks * 4 + 3] = __float_as_uint(hp[ks * 8 + 8 * 132 + 4]);
        }
    }
    __syncthreads();   // buf free for W1

    // stream packed W1 (16384 floats) into buf
    const unsigned sb = (unsigned)__cvta_generic_to_shared(buf);
    #pragma unroll
    for (int it = 0; it < 16; ++it) {
        int q = it * 1024 + tid * 4;
        int x = q >> 7, pk = q & 127;
        cp_async16(sb + (unsigned)(x * BUFW + pk) * 4, g_w1t + q);
    }
    asm volatile("cp.async.commit_group;\n");
    asm volatile("cp.async.wait_group 0;\n");
    __syncthreads();

    float acc[8][4];
    #pragma unroll
    for (int nt = 0; nt < 8; ++nt)
        #pragma unroll
        for (int j = 0; j < 4; ++j) acc[nt][j] = 0.f;

    const float* bbase = buf + (wn * 64 + gg) * BUFW + tt * 2;
    #pragma unroll
    for (int ks = 0; ks < 16; ++ks) {
        #pragma unroll
        for (int nt = 0; nt < 8; ++nt) {
            uint2 bb = *(const uint2*)(bbase + nt * 8 * BUFW + ks * 8);
            mma_tf32(acc[nt], &a_r[ks * 4], bb);
        }
    }

    // bias + relu + tf32-round + store
    #pragma unroll
    for (int nt = 0; nt < 8; ++nt) {
        int col = wn * 64 + nt * 8 + tt * 2;
        float2 bia = *(const float2*)(b1 + col);
        float z0 = to_tf32(fmaxf(acc[nt][0] + bia.x, 0.f));
        float z1 = to_tf32(fmaxf(acc[nt][1] + bia.y, 0.f));
        float z2 = to_tf32(fmaxf(acc[nt][2] + bia.x, 0.f));
        float z3 = to_tf32(fmaxf(acc[nt][3] + bia.y, 0.f));
        *(float2*)(g_h + (size_t)(e0 + wm * 16 + gg)     * 128 + col) = make_float2(z0, z1);
        *(float2*)(g_h + (size_t)(e0 + wm * 16 + gg + 8) * 128 + col) = make_float2(z2, z3);
    }
}

// ---------------------------------------------------------------------------
// K2: fused  w = dlrelu(h @ W2 + b2)  (tf32 mma)  +  per-edge contraction.
// (unchanged from the 475us version)
// ---------------------------------------------------------------------------
#define SWS  65
#define K2_SMEM ((64*BUFW + 64*SWS + 64*48 + 64*16 + 64*48 + 64*3 + 64 + 64) * 4)

__global__ __launch_bounds__(256, 2) void k2_fused(const float* __restrict__ node_attr,
                                                   const float* __restrict__ edge_sh,
                                                   const float* __restrict__ b2) {
    extern __shared__ float smem[];
    float* buf   = smem;                        // [x][pk] 64 x 136
    float* sh_w  = buf   + 64 * BUFW;           // [e][x]  64 x 65
    float* sh_c3 = sh_w  + 64 * SWS;            // ALPHA*xs_i        [e][48]
    float* sh_c2 = sh_c3 + 64 * 48;             // ALPHA*dot_i       [e][16]
    float* sh_c4 = sh_c2 + 64 * 16;             // ALPHA*ss*xv[i][m] [e][48]
    float* sh_sv = sh_c4 + 64 * 48;             // [e][3]
    float* sh_ss = sh_sv + 64 * 3;              // [e]
    int*   sh_dst= (int*)(sh_ss + 64);          // [e]

    const int tid  = threadIdx.x;
    const int e0   = blockIdx.x * 64;
    const int wid  = tid >> 5, lane = tid & 31;
    const int wm   = wid & 3,  wn   = wid >> 2;
    const int gg   = lane >> 2, tt  = lane & 3;
    const int ge   = tid >> 2;
    const int gq   = tid & 3;

    // ---- per-edge coefficients ----
    {
        int e = e0 + ge;
        const float* na = node_attr + (size_t)g_src[e] * 96;
        float4 s4 = *(const float4*)(edge_sh + e * 4);
        float ss = s4.x, sv0 = s4.y, sv1 = s4.z, sv2 = s4.w;
        if (gq == 0) {
            sh_dst[ge] = g_dst[e];
            sh_ss[ge]  = ss;
            sh_sv[ge * 3 + 0] = sv0;
            sh_sv[ge * 3 + 1] = sv1;
            sh_sv[ge * 3 + 2] = sv2;
        }
        #pragma unroll
        for (int j = 0; j < 12; ++j) {
            int i = gq * 12 + j;
            sh_c3[ge * 48 + i] = ALPHA * na[i];
        }
        #pragma unroll
        for (int j = 0; j < 4; ++j) {
            int i = gq * 4 + j;
            float a = na[48 + i * 3 + 0];
            float b = na[48 + i * 3 + 1];
            float c = na[48 + i * 3 + 2];
            sh_c2[ge * 16 + i] = ALPHA * INV_SQRT3 * (a * sv0 + b * sv1 + c * sv2);
            sh_c4[ge * 48 + i * 3 + 0] = ALPHA * ss * a;
            sh_c4[ge * 48 + i * 3 + 1] = ALPHA * ss * b;
            sh_c4[ge * 48 + i * 3 + 2] = ALPHA * ss * c;
        }
    }

    // ---- stage h tile, extract A frags ----
    #pragma unroll
    for (int it = 0; it < 8; ++it) {
        int p = it * 1024 + tid * 4;
        int e = p >> 7, c = p & 127;
        float4 v = *(const float4*)(g_h + (size_t)(e0 + e) * 128 + c);
        *(float4*)&buf[e * 132 + c] = v;
    }
    __syncthreads();

    unsigned a_r[64];
    {
        const float* hp = buf + (wm * 16 + gg) * 132 + tt;
        #pragma unroll
        for (int ks = 0; ks < 16; ++ks) {
            a_r[ks * 4 + 0] = __float_as_uint(hp[ks * 8]);
            a_r[ks * 4 + 1] = __float_as_uint(hp[ks * 8 + 8 * 132]);
            a_r[ks * 4 + 2] = __float_as_uint(hp[ks * 8 + 4]);
            a_r[ks * 4 + 3] = __float_as_uint(hp[ks * 8 + 8 * 132 + 4]);
        }
    }
    __syncthreads();

    float acc_s[12], acc_v[12];
    #pragma unroll
    for (int j = 0; j < 12; ++j) { acc_s[j] = 0.f; acc_v[j] = 0.f; }

    const float* c3row = sh_c3 + ge * 48;
    const float* c2row = sh_c2 + ge * 16;
    const float* c4row = sh_c4 + ge * 48;
    const float* wrow  = sh_w  + ge * SWS;

    const unsigned sb = (unsigned)__cvta_generic_to_shared(buf);
    {
        const float* src = g_w2t;
        #pragma unroll
        for (int it = 0; it < 8; ++it) {
            int q = it * 1024 + tid * 4;
            int x = q >> 7, pk = q & 127;
            cp_async16(sb + (unsigned)(x * BUFW + pk) * 4, src + q);
        }
        asm volatile("cp.async.commit_group;\n");
    }

    const unsigned boff = (unsigned)((wn * 32 + gg) * BUFW + tt * 2);

    #pragma unroll 1
    for (int cc = 0; cc < 64; ++cc) {
        asm volatile("cp.async.wait_group 0;\n");
        __syncthreads();

        float acc[4][4];
        #pragma unroll
        for (int nt = 0; nt < 4; ++nt)
            #pragma unroll
            for (int j = 0; j < 4; ++j) acc[nt][j] = 0.f;

        const float* bbase = buf + boff;
        #pragma unroll
        for (int ks = 0; ks < 16; ++ks) {
            #pragma unroll
            for (int nt = 0; nt < 4; ++nt) {
                uint2 bb = *(const uint2*)(bbase + nt * 8 * BUFW + ks * 8);
                mma_tf32(acc[nt], &a_r[ks * 4], bb);
            }
        }

        #pragma unroll
        for (int nt = 0; nt < 4; ++nt) {
            int colb = wn * 32 + nt * 8 + 2 * tt;
            float2 bia = *(const float2*)(b2 + cc * 64 + colb);
            float z0 = acc[nt][0] + bia.x;
            float z1 = acc[nt][1] + bia.y;
            float z2 = acc[nt][2] + bia.x;
            float z3 = acc[nt][3] + bia.y;
            z0 = (fabsf(z0) <= 10.f) ? z0 : 0.01f * z0;
            z1 = (fabsf(z1) <= 10.f) ? z1 : 0.01f * z1;
            z2 = (fabsf(z2) <= 10.f) ? z2 : 0.01f * z2;
            z3 = (fabsf(z3) <= 10.f) ? z3 : 0.01f * z3;
            sh_w[(wm * 16 + gg)     * SWS + colb]     = z0;
            sh_w[(wm * 16 + gg)     * SWS + colb + 1] = z1;
            sh_w[(wm * 16 + gg + 8) * SWS + colb]     = z2;
            sh_w[(wm * 16 + gg + 8) * SWS + colb + 1] = z3;
        }
        __syncthreads();

        if (cc < 63) {
            const float* src = g_w2t + (size_t)(cc + 1) * 8192;
            #pragma unroll
            for (int it = 0; it < 8; ++it) {
                int q = it * 1024 + tid * 4;
                int x = q >> 7, pk = q & 127;
                cp_async16(sb + (unsigned)(x * BUFW + pk) * 4, src + q);
            }
            asm volatile("cp.async.commit_group;\n");
        }

        if (cc < 36) {                         // w_ss
            int base = cc * 64;
            int i0   = base / 48;
            int off  = base - i0 * 48;
            float ssv = sh_ss[ge];
            float ci0 = ssv * c3row[i0];
            float ci1 = (i0 + 1 < 48) ? ssv * c3row[i0 + 1] : 0.f;
            #pragma unroll
            for (int j = 0; j < 12; ++j) {
                int k  = gq * 12 + j;
                int l0 = k - off;
                if (l0 >= 0)      acc_s[j] += ci0 * wrow[l0];
                if (l0 + 48 < 64) acc_s[j] += ci1 * wrow[l0 + 48];
            }
        } else if (cc < 48) {                  // w_vs
            int tb  = cc * 64 - 2304;
            int i0  = tb / 48;
            int off = tb - i0 * 48;
            float ci0 = c2row[i0];
            float ci1 = (i0 + 1 < 16) ? c2row[i0 + 1] : 0.f;
            #pragma unroll
            for (int j = 0; j < 12; ++j) {
                int k  = gq * 12 + j;
                int l0 = k - off;
                if (l0 >= 0)      acc_s[j] += ci0 * wrow[l0];
                if (l0 + 48 < 64) acc_s[j] += ci1 * wrow[l0 + 48];
            }
        } else if (cc < 60) {                  // w_sv
            int i0 = 4 * (cc - 48);
            float c30 = c3row[i0], c31 = c3row[i0 + 1];
            float c32 = c3row[i0 + 2], c33 = c3row[i0 + 3];
            float sv0 = sh_sv[ge * 3], sv1 = sh_sv[ge * 3 + 1], sv2 = sh_sv[ge * 3 + 2];
            #pragma unroll
            for (int kk = 0; kk < 4; ++kk) {
                int k = gq * 4 + kk;
                float s = c30 * wrow[k] + c31 * wrow[16 + k]
                        + c32 * wrow[32 + k] + c33 * wrow[48 + k];
                acc_v[kk * 3 + 0] += s * sv0;
                acc_v[kk * 3 + 1] += s * sv1;
                acc_v[kk * 3 + 2] += s * sv2;
            }
        } else {                               // w_vv
            int i0 = 4 * (cc - 60);
            const float* c4p = c4row + i0 * 3;
            #pragma unroll
            for (int kk = 0; kk < 4; ++kk) {
                int k = gq * 4 + kk;
                float w0 = wrow[k],      w1 = wrow[16 + k];
                float w2 = wrow[32 + k], w3 = wrow[48 + k];
                acc_v[kk * 3 + 0] += c4p[0] * w0 + c4p[3] * w1 + c4p[6] * w2 + c4p[9]  * w3;
                acc_v[kk * 3 + 1] += c4p[1] * w0 + c4p[4] * w1 + c4p[7] * w2 + c4p[10] * w3;
                acc_v[kk * 3 + 2] += c4p[2] * w0 + c4p[5] * w1 + c4p[8] * w2 + c4p[11] * w3;
            }
        }
    }

    int dst = sh_dst[ge];
    float* gp = g_acc + (size_t)dst * 96;
    #pragma unroll
    for (int j = 0; j < 12; ++j) atomicAdd(gp + gq * 12 + j, acc_s[j]);
    #pragma unroll
    for (int j = 0; j < 12; ++j) atomicAdd(gp + 48 + gq * 12 + j, acc_v[j]);
}

// ---------------------------------------------------------------------------
// K3: batchnorm statistics
// ---------------------------------------------------------------------------
__global__ __launch_bounds__(256) void k3_stats(const float* __restrict__ bnw,
                                                const float* __restrict__ bnb) {
    __shared__ double rs[256], rs2[256];
    int b = blockIdx.x, tid = threadIdx.x;
    double s = 0.0, s2 = 0.0;
    if (b < 48) {
        for (int n = tid; n < NN; n += 256) {
            float x = g_acc[(size_t)n * 96 + b];
            s  += (double)x;
            s2 += (double)x * (double)x;
        }
    } else {
        int j = b - 48;
        for (int n = tid; n < NN; n += 256) {
            const float* p = &g_acc[(size_t)n * 96 + 48 + j * 3];
            s2 += (double)p[0] * p[0] + (double)p[1] * p[1] + (double)p[2] * p[2];
        }
    }
    rs[tid] = s; rs2[tid] = s2;
    __syncthreads();
    for (int st = 128; st > 0; st >>= 1) {
        if (tid < st) { rs[tid] += rs[tid + st]; rs2[tid] += rs2[tid + st]; }
        __syncthreads();
    }
    if (tid == 0) {
        if (b < 48) {
            double mean = rs[0] / (double)NN;
            double var  = rs2[0] / (double)NN - mean * mean;
            double scale = (double)bnw[b] / sqrt(var + 1e-5);
            g_scale[b] = (float)scale;
            g_shift[b] = bnb[b] - (float)(mean * scale);
        } else {
            double vn = rs2[0] / ((double)NN * 3.0);
            g_scale[b] = (float)((double)bnw[b] / sqrt(vn + 1e-5));
        }
    }
}

// ---------------------------------------------------------------------------
// K4: apply normalization -> d_out
// ---------------------------------------------------------------------------
__global__ void k4_apply(float* __restrict__ out) {
    int idx = blockIdx.x * 256 + threadIdx.x;
    float x = g_acc[idx];
    int f = idx % 96;
    float r;
    if (f < 48) r = x * g_scale[f] + g_shift[f];
    else        r = x * g_scale[48 + (f - 48) / 3];
    out[idx] = r;
}

// ---------------------------------------------------------------------------
extern "C" void kernel_launch(void* const* d_in, const int* in_sizes, int n_in,
                              void* d_out, int out_size) {
    const float* node_attr = (const float*)d_in[0];
    const int*   eidx      = (const int*)d_in[1];   // int32 OR int64 (auto-detected)
    const float* edge_attr = (const float*)d_in[2];
    const float* edge_sh   = (const float*)d_in[3];
    const float* W1        = (const float*)d_in[4];
    const float* b1        = (const float*)d_in[5];
    const float* W2        = (const float*)d_in[6];
    const float* b2        = (const float*)d_in[7];
    const float* bnw       = (const float*)d_in[8];
    const float* bnb       = (const float*)d_in[9];
    float*       out       = (float*)d_out;

    cudaFuncSetAttribute(k1_gemm,  cudaFuncAttributeMaxDynamicSharedMemorySize, K1_SMEM);
    cudaFuncSetAttribute(k2_fused, cudaFuncAttributeMaxDynamicSharedMemorySize, K2_SMEM);

    k_pre   <<<1728, 256>>>(eidx, node_attr, W1);
    k_w2t   <<<64, 256>>>(W2);
    k1_gemm <<<EE / 64, 256, K1_SMEM>>>(edge_attr, b1);
    k2_fused<<<EE / 64, 256, K2_SMEM>>>(node_attr, edge_sh, b2);
    k3_stats<<<64, 256>>>(bnw, bnb);
    k4_apply<<<(NN * 96) / 256, 256>>>(out);
}